// round 7
// baseline (speedup 1.0000x reference)
#include <cuda_runtime.h>
#include <cuda_fp16.h>
#include <math.h>
#include <stdint.h>

#define CB   512
#define CS   120
#define CD   216
#define CH   1024
#define CML  24

#define NCH   20        // 4 x-chunks (K 216->256 padded) + 16 h-chunks, K=64 each
#define NCH_X 4
#define NT    32        // N tiles of 128 cols (4 gates x 32 j)
#define MT    64        // M tile per CTA
#define XSTR  256       // padded x-plane stride

// A-only staging: 8KB per stage, 4 stages
#define ABUF 8192
#define NSTAGE 4
#define SGJ 33
#define SMEM_STEP 33792   // max(4*8192=32768, sg 4*64*33*4=33792)

// ---------------- device globals ----------------
// W in B-fragment layout: uint4[ ((nt*4+gate)*NCH + ch)*4 + k16 ][64]  (lane*2 + {0,1})
__device__ __align__(16) uint4 g_Wfrag[(size_t)NT * 4 * NCH * 4 * 64];   // 10.5MB
__device__ __align__(16) __half g_src[(size_t)CS * CB * XSTR];
__device__ __align__(16) __half g_xd[(size_t)CB * XSTR];
__device__ __align__(16) __half g_h[2][(size_t)CB * CH];
__device__ float g_c[(size_t)CB * CH];
__device__ float g_bias[4 * CH];

// ---------------- helpers ----------------
__device__ __forceinline__ uint32_t smem_u32(const void* p) {
    uint32_t a;
    asm("{ .reg .u64 t; cvta.to.shared.u64 t, %1; cvt.u32.u64 %0, t; }" : "=r"(a) : "l"(p));
    return a;
}
__device__ __forceinline__ void ldsm4(uint32_t* r, uint32_t addr) {
    asm volatile("ldmatrix.sync.aligned.m8n8.x4.shared.b16 {%0,%1,%2,%3}, [%4];"
        : "=r"(r[0]), "=r"(r[1]), "=r"(r[2]), "=r"(r[3]) : "r"(addr));
}
__device__ __forceinline__ void mma_h(float* d, const uint32_t* a, uint32_t b0, uint32_t b1) {
    asm volatile("mma.sync.aligned.m16n8k16.row.col.f32.f16.f16.f32 "
        "{%0,%1,%2,%3}, {%4,%5,%6,%7}, {%8,%9}, {%0,%1,%2,%3};"
        : "+f"(d[0]), "+f"(d[1]), "+f"(d[2]), "+f"(d[3])
        : "r"(a[0]), "r"(a[1]), "r"(a[2]), "r"(a[3]), "r"(b0), "r"(b1));
}
#define CP16(dst, src) \
    asm volatile("cp.async.cg.shared.global [%0], [%1], 16;" :: "r"(dst), "l"(src))
#define CP_COMMIT() asm volatile("cp.async.commit_group;" ::: "memory")
#define CP_WAIT(n)  asm volatile("cp.async.wait_group %0;" :: "n"(n) : "memory")

__device__ __forceinline__ float sigf(float x) { return 1.0f / (1.0f + __expf(-x)); }

// ---------------- init / precompute ----------------
__global__ void init_kernel(const float* __restrict__ b_ih, const float* __restrict__ b_hh) {
    int idx = blockIdx.x * blockDim.x + threadIdx.x;
    if (idx < CB * CH) {
        g_c[idx] = 0.0f;
        g_h[0][idx] = __float2half_rn(0.0f);
    }
    if (idx < CB * XSTR) g_xd[idx] = __float2half_rn(0.0f);
    if (idx < 4 * CH) g_bias[idx] = b_ih[idx] + b_hh[idx];
}

__global__ void src_split_kernel(const float* __restrict__ src) {
    size_t idx = (size_t)blockIdx.x * blockDim.x + threadIdx.x;
    if (idx >= (size_t)CS * CB * XSTR) return;
    int c = (int)(idx & (XSTR - 1));
    int r = (int)((idx >> 8) & (CB - 1));
    int t = (int)(idx >> 17);
    float v = (c < CD) ? src[((size_t)r * CS + t) * CD + c] : 0.0f;
    g_src[idx] = __float2half_rn(v);
}

// W -> B-fragment layout (fp16). One thread per uint2 (4 fp16: k0,k1,k8,k9).
__global__ void prep_w_kernel(const float* __restrict__ W_ih, const float* __restrict__ W_hh) {
    int s = blockIdx.x * blockDim.x + threadIdx.x;
    const int TOT = NT * 4 * NCH * 4 * 128;   // 1,310,720 uint2s
    if (s >= TOT) return;
    int nb   = s & 3;
    int lane = (s >> 2) & 31;
    int k16  = (s >> 7) & 3;
    int rest = s >> 9;
    int ch = rest % NCH; rest /= NCH;
    int wc = rest & 3;          // gate
    int nt = rest >> 2;

    int j = nt * 32 + nb * 8 + (lane >> 2);
    int R = wc * CH + j;
    int k0 = k16 * 16 + (lane & 3) * 2;

    float v[4];
    if (ch < NCH_X) {
        int kb = ch * 64 + k0;
        int ks[4] = {kb, kb + 1, kb + 8, kb + 9};
#pragma unroll
        for (int q = 0; q < 4; ++q)
            v[q] = (ks[q] < CD) ? W_ih[(size_t)R * CD + ks[q]] : 0.0f;
    } else {
        const float* wr = W_hh + (size_t)R * CH + (ch - NCH_X) * 64 + k0;
        v[0] = wr[0]; v[1] = wr[1]; v[2] = wr[8]; v[3] = wr[9];
    }
    uint32_t lo = (uint32_t)__half_as_ushort(__float2half_rn(v[0])) |
                  ((uint32_t)__half_as_ushort(__float2half_rn(v[1])) << 16);
    uint32_t hi = (uint32_t)__half_as_ushort(__float2half_rn(v[2])) |
                  ((uint32_t)__half_as_ushort(__float2half_rn(v[3])) << 16);
    size_t dest = ((((size_t)(nt * 4 + wc) * NCH + ch) * 4 + k16)) * 128 + lane * 4 + nb;
    ((uint2*)g_Wfrag)[dest] = make_uint2(lo, hi);
}

// ---------------- fused LSTM step: A via smem/ldsm, W via LDG fragments ----------------
__global__ __launch_bounds__(256, 2)
void lstm_step(int use_xd, int t, int rd, int wr)
{
    extern __shared__ char smem[];
    const uint32_t sb = smem_u32(smem);
    const int tid = threadIdx.x;
    const int lane = tid & 31;
    const int w = tid >> 5;
    const int wm = w & 1;          // 2 row groups of 32
    const int wn = w >> 1;         // gate 0..3
    const int nt = blockIdx.x;
    const int mb = blockIdx.y * MT;

    const __half* xp = use_xd ? g_xd : (g_src + (size_t)t * CB * XSTR);
    const __half* hp = g_h[rd];

    // cp.async A mapping: 512 granules of 16B, 2 per thread (A region 8KB)
    int ar[2], acb[2];
    uint32_t aoff[2];
#pragma unroll
    for (int it = 0; it < 2; ++it) {
        int idx = tid + it * 256;
        ar[it]  = idx >> 3;        // 0..63
        acb[it] = idx & 7;
        aoff[it] = (uint32_t)(ar[it] * 128 + ((acb[it] ^ (ar[it] & 7)) << 4));
    }

    auto issue_chunk = [&](int ch, uint32_t buf) {
        const __half* p0;
        int stride, koff;
        if (ch < NCH_X) { p0 = xp; stride = XSTR; koff = ch * 64; }
        else            { p0 = hp; stride = CH;   koff = (ch - NCH_X) * 64; }
#pragma unroll
        for (int it = 0; it < 2; ++it) {
            const __half* sp = p0 + (size_t)(mb + ar[it]) * stride + koff + acb[it] * 8;
            CP16(buf + aoff[it], sp);
        }
    };

    // A ldsm base patterns (warp tile 32 rows x 32 cols)
    uint32_t abase[2]; int amask[2];
#pragma unroll
    for (int mg = 0; mg < 2; ++mg) {
        int rr = wm * 32 + mg * 16 + (lane & 15);
        abase[mg] = (uint32_t)(rr * 128);
        amask[mg] = rr & 7;
    }
    const int akc_half = lane >> 4;

    // W fragment pointer (uint4 units)
    const uint4* wbase = g_Wfrag + ((size_t)(nt * 4 + wn) * NCH) * 4 * 64 + lane * 2;

    float acc[2][4][4];
#pragma unroll
    for (int mg = 0; mg < 2; ++mg)
#pragma unroll
        for (int nb = 0; nb < 4; ++nb)
#pragma unroll
            for (int e = 0; e < 4; ++e) acc[mg][nb][e] = 0.0f;

    // A prologue: 3 stages in flight
    issue_chunk(0, sb);            CP_COMMIT();
    issue_chunk(1, sb + ABUF);     CP_COMMIT();
    issue_chunk(2, sb + 2 * ABUF); CP_COMMIT();

    // W prologue: first k16 fragments
    uint4 wc0 = __ldg(wbase);
    uint4 wc1 = __ldg(wbase + 1);

#pragma unroll 1
    for (int ch = 0; ch < NCH; ++ch) {
        const uint32_t buf = sb + (uint32_t)(ch & 3) * ABUF;
        CP_WAIT(2);
        __syncthreads();
        if (ch + 3 < NCH) issue_chunk(ch + 3, sb + (uint32_t)((ch + 3) & 3) * ABUF);
        CP_COMMIT();   // empty group ok: keeps flight count at 3

#pragma unroll
        for (int k16 = 0; k16 < 4; ++k16) {
            // prefetch next k16 W fragments
            uint4 wn0, wn1;
            {
                int nidx = ch * 4 + k16 + 1;
                if (nidx < NCH * 4) {
                    const uint4* np = wbase + (size_t)nidx * 64;
                    wn0 = __ldg(np);
                    wn1 = __ldg(np + 1);
                }
            }
            uint32_t ah[2][4];
            const uint32_t kcA = (uint32_t)(2 * k16 + akc_half);
#pragma unroll
            for (int mg = 0; mg < 2; ++mg)
                ldsm4(ah[mg], buf + abase[mg] + ((kcA ^ (uint32_t)amask[mg]) << 4));

            uint32_t b0[4] = {wc0.x, wc0.z, wc1.x, wc1.z};
            uint32_t b1[4] = {wc0.y, wc0.w, wc1.y, wc1.w};
#pragma unroll
            for (int mg = 0; mg < 2; ++mg)
#pragma unroll
                for (int nb = 0; nb < 4; ++nb)
                    mma_h(acc[mg][nb], ah[mg], b0[nb], b1[nb]);
            wc0 = wn0; wc1 = wn1;
        }
    }
    __syncthreads();   // all ldsm consumption done before sg overwrite

    // gate exchange (reuse smem): sg[4 gates * 64 rows][SGJ]
    float* sg = (float*)smem;
#pragma unroll
    for (int mg = 0; mg < 2; ++mg)
#pragma unroll
        for (int nb = 0; nb < 4; ++nb) {
            int r0 = wm * 32 + mg * 16 + (lane >> 2);
            int jj = nb * 8 + (lane & 3) * 2;
            float* p0 = &sg[((size_t)(wn * 64 + r0)) * SGJ + jj];
            p0[0] = acc[mg][nb][0]; p0[1] = acc[mg][nb][1];
            float* p1 = p0 + 8 * SGJ;
            p1[0] = acc[mg][nb][2]; p1[1] = acc[mg][nb][3];
        }
    __syncthreads();

    // cell update: 64 rows x 32 j -> 256 threads x (1 row, 8 j)
    {
        int row = tid >> 2;
        int j0 = (tid & 3) * 8;
        int jcol = nt * 32 + j0;
        size_t off = (size_t)(mb + row) * CH + jcol;

        float gv[4][8];
#pragma unroll
        for (int g = 0; g < 4; ++g) {
            const float* p = &sg[((size_t)(g * 64 + row)) * SGJ + j0];
#pragma unroll
            for (int e = 0; e < 8; ++e) gv[g][e] = p[e] + g_bias[g * CH + jcol + e];
        }
        float4 cA = *(const float4*)(g_c + off);
        float4 cB = *(const float4*)(g_c + off + 4);
        float cold[8] = {cA.x, cA.y, cA.z, cA.w, cB.x, cB.y, cB.z, cB.w};
        float cn[8], hn[8];
#pragma unroll
        for (int e = 0; e < 8; ++e) {
            float ci = sigf(gv[0][e]);
            float cf = sigf(gv[1][e]);
            float cg = tanhf(gv[2][e]);
            float co = sigf(gv[3][e]);
            cn[e] = cf * cold[e] + ci * cg;
            hn[e] = co * tanhf(cn[e]);
        }
        *(float4*)(g_c + off)     = make_float4(cn[0], cn[1], cn[2], cn[3]);
        *(float4*)(g_c + off + 4) = make_float4(cn[4], cn[5], cn[6], cn[7]);

        uint32_t ph[4];
#pragma unroll
        for (int e2 = 0; e2 < 4; ++e2) {
            __half ha = __float2half_rn(hn[e2 * 2]);
            __half hb = __float2half_rn(hn[e2 * 2 + 1]);
            ph[e2] = (uint32_t)__half_as_ushort(ha) | ((uint32_t)__half_as_ushort(hb) << 16);
        }
        *(uint4*)(&g_h[wr][off]) = make_uint4(ph[0], ph[1], ph[2], ph[3]);
    }
}

// ---------------- decoder projection ----------------
__global__ __launch_bounds__(256)
void proj_kernel(int hbuf,
                 const float* __restrict__ W_out,
                 const float* __restrict__ b_out,
                 float* __restrict__ outp)
{
    int lane = threadIdx.x & 31;
    int w = threadIdx.x >> 5;
    int d = blockIdx.x * 8 + w;
    int r0 = blockIdx.y * 8;
    const __half* hp = g_h[hbuf];
    int k0 = lane * 32;

    float wv[32];
    {
        const float4* wp = (const float4*)(W_out + (size_t)d * CH + k0);
#pragma unroll
        for (int q = 0; q < 8; ++q) {
            float4 f = wp[q];
            wv[q * 4 + 0] = f.x; wv[q * 4 + 1] = f.y; wv[q * 4 + 2] = f.z; wv[q * 4 + 3] = f.w;
        }
    }
    float acc[8];
#pragma unroll
    for (int r = 0; r < 8; ++r) {
        const uint4* hq = (const uint4*)(hp + (size_t)(r0 + r) * CH + k0);
        float s = 0.0f;
#pragma unroll
        for (int q = 0; q < 4; ++q) {
            uint4 hv = hq[q];
            const __half2* h2 = (const __half2*)&hv;
#pragma unroll
            for (int e = 0; e < 4; ++e) {
                float2 a = __half22float2(h2[e]);
                int kk = q * 8 + e * 2;
                s += a.x * wv[kk] + a.y * wv[kk + 1];
            }
        }
        acc[r] = s;
    }
#pragma unroll
    for (int r = 0; r < 8; ++r) {
#pragma unroll
        for (int off = 16; off > 0; off >>= 1)
            acc[r] += __shfl_xor_sync(0xFFFFFFFFu, acc[r], off);
    }
    if (lane == 0) {
        float bo = b_out[d];
#pragma unroll
        for (int r = 0; r < 8; ++r) {
            float y = acc[r] + bo;
            int row = r0 + r;
            outp[(size_t)row * CML * CD + d] = y;
            g_xd[(size_t)row * XSTR + d] = __float2half_rn(y);
        }
    }
}

extern "C" void kernel_launch(void* const* d_in, const int* in_sizes, int n_in,
                              void* d_out, int out_size)
{
    (void)in_sizes; (void)n_in; (void)out_size;
    const float* src   = (const float*)d_in[0];
    const float* W_ih  = (const float*)d_in[1];
    const float* W_hh  = (const float*)d_in[2];
    const float* b_ih  = (const float*)d_in[3];
    const float* b_hh  = (const float*)d_in[4];
    const float* W_out = (const float*)d_in[5];
    const float* b_out = (const float*)d_in[6];
    float* out = (float*)d_out;

    static int once = 0;
    if (!once) {
        cudaFuncSetAttribute(lstm_step, cudaFuncAttributeMaxDynamicSharedMemorySize, SMEM_STEP);
        once = 1;
    }

    init_kernel<<<(CB * CH + 255) / 256, 256>>>(b_ih, b_hh);
    {
        size_t tot = (size_t)CS * CB * XSTR;
        src_split_kernel<<<(unsigned)((tot + 255) / 256), 256>>>(src);
    }
    {
        int tot = NT * 4 * NCH * 4 * 128;
        prep_w_kernel<<<(tot + 255) / 256, 256>>>(W_ih, W_hh);
    }

    dim3 sgrid(NT, CB / MT);   // 32 x 8 = 256 CTAs
    dim3 pgrid(27, CB / 8);    // 27 x 64

    int p = 0;
    for (int t = 0; t < CS; ++t) {
        lstm_step<<<sgrid, 256, SMEM_STEP>>>(0, t, p, p ^ 1);
        p ^= 1;
    }
    for (int s = 0; s < CML; ++s) {
        if (s == 0) lstm_step<<<sgrid, 256, SMEM_STEP>>>(0, CS - 1, p, p ^ 1);
        else        lstm_step<<<sgrid, 256, SMEM_STEP>>>(1, 0, p, p ^ 1);
        proj_kernel<<<pgrid, 256>>>(p ^ 1, W_out, b_out, out + (size_t)s * CD);
        p ^= 1;
    }
}

// round 8
// speedup vs baseline: 1.0746x; 1.0746x over previous
#include <cuda_runtime.h>
#include <cuda_fp16.h>
#include <math.h>
#include <stdint.h>

#define CB   512
#define CS   120
#define CD   216
#define CH   1024
#define CML  24

#define NCH   20        // 4 x-chunks (K 216->256 padded) + 16 h-chunks, K=64 each
#define NCH_X 4
#define NT    32        // N tiles of 128 cols (4 gates x 32 j)
#define MT    64        // M tile per CTA
#define XSTR  256       // padded x-plane stride
#define NK16  (NCH * 4) // 80 flat k16 steps

// A-only staging: 8KB per stage, 4 stages
#define ABUF 8192
#define SGJ 33
#define SMEM_STEP 33792   // max(4*8192=32768, sg 4*64*33*4=33792)

// ---------------- device globals ----------------
// W in B-fragment layout: uint4[ ((nt*4+gate)*NCH + ch)*4 + k16 ][64]  (lane*2 + {0,1})
__device__ __align__(16) uint4 g_Wfrag[(size_t)NT * 4 * NCH * 4 * 64];   // 10.5MB
__device__ __align__(16) __half g_src[(size_t)CS * CB * XSTR];
__device__ __align__(16) __half g_xd[(size_t)CB * XSTR];
__device__ __align__(16) __half g_h[2][(size_t)CB * CH];
__device__ float g_c[(size_t)CB * CH];
__device__ float g_bias[4 * CH];

// ---------------- helpers ----------------
__device__ __forceinline__ uint32_t smem_u32(const void* p) {
    uint32_t a;
    asm("{ .reg .u64 t; cvta.to.shared.u64 t, %1; cvt.u32.u64 %0, t; }" : "=r"(a) : "l"(p));
    return a;
}
__device__ __forceinline__ void ldsm4(uint32_t* r, uint32_t addr) {
    asm volatile("ldmatrix.sync.aligned.m8n8.x4.shared.b16 {%0,%1,%2,%3}, [%4];"
        : "=r"(r[0]), "=r"(r[1]), "=r"(r[2]), "=r"(r[3]) : "r"(addr));
}
__device__ __forceinline__ void mma_h(float* d, const uint32_t* a, uint32_t b0, uint32_t b1) {
    asm volatile("mma.sync.aligned.m16n8k16.row.col.f32.f16.f16.f32 "
        "{%0,%1,%2,%3}, {%4,%5,%6,%7}, {%8,%9}, {%0,%1,%2,%3};"
        : "+f"(d[0]), "+f"(d[1]), "+f"(d[2]), "+f"(d[3])
        : "r"(a[0]), "r"(a[1]), "r"(a[2]), "r"(a[3]), "r"(b0), "r"(b1));
}
#define CP16(dst, src) \
    asm volatile("cp.async.cg.shared.global [%0], [%1], 16;" :: "r"(dst), "l"(src))
#define CP_COMMIT() asm volatile("cp.async.commit_group;" ::: "memory")
#define CP_WAIT(n)  asm volatile("cp.async.wait_group %0;" :: "n"(n) : "memory")

__device__ __forceinline__ float sigf(float x) { return 1.0f / (1.0f + __expf(-x)); }

// ---------------- init / precompute ----------------
__global__ void init_kernel(const float* __restrict__ b_ih, const float* __restrict__ b_hh) {
    int idx = blockIdx.x * blockDim.x + threadIdx.x;
    if (idx < CB * CH) {
        g_c[idx] = 0.0f;
        g_h[0][idx] = __float2half_rn(0.0f);
    }
    if (idx < CB * XSTR) g_xd[idx] = __float2half_rn(0.0f);
    if (idx < 4 * CH) g_bias[idx] = b_ih[idx] + b_hh[idx];
}

__global__ void src_split_kernel(const float* __restrict__ src) {
    size_t idx = (size_t)blockIdx.x * blockDim.x + threadIdx.x;
    if (idx >= (size_t)CS * CB * XSTR) return;
    int c = (int)(idx & (XSTR - 1));
    int r = (int)((idx >> 8) & (CB - 1));
    int t = (int)(idx >> 17);
    float v = (c < CD) ? src[((size_t)r * CS + t) * CD + c] : 0.0f;
    g_src[idx] = __float2half_rn(v);
}

// W -> B-fragment layout (fp16). One thread per uint2 (4 fp16: k0,k1,k8,k9).
__global__ void prep_w_kernel(const float* __restrict__ W_ih, const float* __restrict__ W_hh) {
    int s = blockIdx.x * blockDim.x + threadIdx.x;
    const int TOT = NT * 4 * NCH * 4 * 128;   // 1,310,720 uint2s
    if (s >= TOT) return;
    int nb   = s & 3;
    int lane = (s >> 2) & 31;
    int k16  = (s >> 7) & 3;
    int rest = s >> 9;
    int ch = rest % NCH; rest /= NCH;
    int wc = rest & 3;          // gate
    int nt = rest >> 2;

    int j = nt * 32 + nb * 8 + (lane >> 2);
    int R = wc * CH + j;
    int k0 = k16 * 16 + (lane & 3) * 2;

    float v[4];
    if (ch < NCH_X) {
        int kb = ch * 64 + k0;
        int ks[4] = {kb, kb + 1, kb + 8, kb + 9};
#pragma unroll
        for (int q = 0; q < 4; ++q)
            v[q] = (ks[q] < CD) ? W_ih[(size_t)R * CD + ks[q]] : 0.0f;
    } else {
        const float* wr = W_hh + (size_t)R * CH + (ch - NCH_X) * 64 + k0;
        v[0] = wr[0]; v[1] = wr[1]; v[2] = wr[8]; v[3] = wr[9];
    }
    uint32_t lo = (uint32_t)__half_as_ushort(__float2half_rn(v[0])) |
                  ((uint32_t)__half_as_ushort(__float2half_rn(v[1])) << 16);
    uint32_t hi = (uint32_t)__half_as_ushort(__float2half_rn(v[2])) |
                  ((uint32_t)__half_as_ushort(__float2half_rn(v[3])) << 16);
    size_t dest = ((((size_t)(nt * 4 + wc) * NCH + ch) * 4 + k16)) * 128 + lane * 4 + nb;
    ((uint2*)g_Wfrag)[dest] = make_uint2(lo, hi);
}

// ---------------- fused LSTM step: A via smem/ldsm, W via LDG ring (depth 4) ----------------
__global__ __launch_bounds__(256, 2)
void lstm_step(int use_xd, int t, int rd, int wr)
{
    extern __shared__ char smem[];
    const uint32_t sb = smem_u32(smem);
    const int tid = threadIdx.x;
    const int lane = tid & 31;
    const int w = tid >> 5;
    const int wm = w & 1;          // 2 row groups of 32
    const int wn = w >> 1;         // gate 0..3
    const int nt = blockIdx.x;
    const int mb = blockIdx.y * MT;

    const __half* xp = use_xd ? g_xd : (g_src + (size_t)t * CB * XSTR);
    const __half* hp = g_h[rd];

    // cp.async A mapping: 512 granules of 16B, 2 per thread (A region 8KB)
    int ar[2], acb[2];
    uint32_t aoff[2];
#pragma unroll
    for (int it = 0; it < 2; ++it) {
        int idx = tid + it * 256;
        ar[it]  = idx >> 3;        // 0..63
        acb[it] = idx & 7;
        aoff[it] = (uint32_t)(ar[it] * 128 + ((acb[it] ^ (ar[it] & 7)) << 4));
    }

    auto issue_chunk = [&](int ch, uint32_t buf) {
        const __half* p0;
        int stride, koff;
        if (ch < NCH_X) { p0 = xp; stride = XSTR; koff = ch * 64; }
        else            { p0 = hp; stride = CH;   koff = (ch - NCH_X) * 64; }
#pragma unroll
        for (int it = 0; it < 2; ++it) {
            const __half* sp = p0 + (size_t)(mb + ar[it]) * stride + koff + acb[it] * 8;
            CP16(buf + aoff[it], sp);
        }
    };

    // A ldsm base patterns (warp tile 32 rows x 32 cols)
    uint32_t abase[2]; int amask[2];
#pragma unroll
    for (int mg = 0; mg < 2; ++mg) {
        int rr = wm * 32 + mg * 16 + (lane & 15);
        abase[mg] = (uint32_t)(rr * 128);
        amask[mg] = rr & 7;
    }
    const int akc_half = lane >> 4;

    // W fragment pointer (uint4 units); consecutive flat k16 index strides 64 uint4s
    const uint4* wbase = g_Wfrag + ((size_t)(nt * 4 + wn) * NCH) * 4 * 64 + lane * 2;

    float acc[2][4][4];
#pragma unroll
    for (int mg = 0; mg < 2; ++mg)
#pragma unroll
        for (int nb = 0; nb < 4; ++nb)
#pragma unroll
            for (int e = 0; e < 4; ++e) acc[mg][nb][e] = 0.0f;

    // A prologue: 3 stages in flight
    issue_chunk(0, sb);            CP_COMMIT();
    issue_chunk(1, sb + ABUF);     CP_COMMIT();
    issue_chunk(2, sb + 2 * ABUF); CP_COMMIT();

    // W prologue: ring slots 0..2 <- flat k16 0..2
    uint4 wr0[4], wr1[4];
#pragma unroll
    for (int s = 0; s < 3; ++s) {
        const uint4* np = wbase + (size_t)s * 64;
        wr0[s] = __ldg(np);
        wr1[s] = __ldg(np + 1);
    }

#pragma unroll 1
    for (int ch = 0; ch < NCH; ++ch) {
        const uint32_t buf = sb + (uint32_t)(ch & 3) * ABUF;
        CP_WAIT(2);
        __syncthreads();
        if (ch + 3 < NCH) issue_chunk(ch + 3, sb + (uint32_t)((ch + 3) & 3) * ABUF);
        CP_COMMIT();   // empty group ok: keeps flight count constant

#pragma unroll
        for (int k16 = 0; k16 < 4; ++k16) {
            // prefetch flat index f+3 into ring slot (k16+3)&3 (slot is free: consumed last step)
            {
                int nf = ch * 4 + k16 + 3;
                const int ns = (k16 + 3) & 3;
                if (nf < NK16) {
                    const uint4* np = wbase + (size_t)nf * 64;
                    wr0[ns] = __ldg(np);
                    wr1[ns] = __ldg(np + 1);
                }
            }
            // A fragments from smem
            uint32_t ah[2][4];
            const uint32_t kcA = (uint32_t)(2 * k16 + akc_half);
#pragma unroll
            for (int mg = 0; mg < 2; ++mg)
                ldsm4(ah[mg], buf + abase[mg] + ((kcA ^ (uint32_t)amask[mg]) << 4));

            // consume ring slot k16
            uint32_t b0[4] = {wr0[k16].x, wr0[k16].z, wr1[k16].x, wr1[k16].z};
            uint32_t b1[4] = {wr0[k16].y, wr0[k16].w, wr1[k16].y, wr1[k16].w};
#pragma unroll
            for (int mg = 0; mg < 2; ++mg)
#pragma unroll
                for (int nb = 0; nb < 4; ++nb)
                    mma_h(acc[mg][nb], ah[mg], b0[nb], b1[nb]);
        }
    }
    __syncthreads();   // all ldsm consumption done before sg overwrite

    // gate exchange (reuse smem): sg[4 gates * 64 rows][SGJ]
    float* sg = (float*)smem;
#pragma unroll
    for (int mg = 0; mg < 2; ++mg)
#pragma unroll
        for (int nb = 0; nb < 4; ++nb) {
            int r0 = wm * 32 + mg * 16 + (lane >> 2);
            int jj = nb * 8 + (lane & 3) * 2;
            float* p0 = &sg[((size_t)(wn * 64 + r0)) * SGJ + jj];
            p0[0] = acc[mg][nb][0]; p0[1] = acc[mg][nb][1];
            float* p1 = p0 + 8 * SGJ;
            p1[0] = acc[mg][nb][2]; p1[1] = acc[mg][nb][3];
        }
    __syncthreads();

    // cell update: 64 rows x 32 j -> 256 threads x (1 row, 8 j)
    {
        int row = tid >> 2;
        int j0 = (tid & 3) * 8;
        int jcol = nt * 32 + j0;
        size_t off = (size_t)(mb + row) * CH + jcol;

        float gv[4][8];
#pragma unroll
        for (int g = 0; g < 4; ++g) {
            const float* p = &sg[((size_t)(g * 64 + row)) * SGJ + j0];
#pragma unroll
            for (int e = 0; e < 8; ++e) gv[g][e] = p[e] + g_bias[g * CH + jcol + e];
        }
        float4 cA = *(const float4*)(g_c + off);
        float4 cB = *(const float4*)(g_c + off + 4);
        float cold[8] = {cA.x, cA.y, cA.z, cA.w, cB.x, cB.y, cB.z, cB.w};
        float cn[8], hn[8];
#pragma unroll
        for (int e = 0; e < 8; ++e) {
            float ci = sigf(gv[0][e]);
            float cf = sigf(gv[1][e]);
            float cg = tanhf(gv[2][e]);
            float co = sigf(gv[3][e]);
            cn[e] = cf * cold[e] + ci * cg;
            hn[e] = co * tanhf(cn[e]);
        }
        *(float4*)(g_c + off)     = make_float4(cn[0], cn[1], cn[2], cn[3]);
        *(float4*)(g_c + off + 4) = make_float4(cn[4], cn[5], cn[6], cn[7]);

        uint32_t ph[4];
#pragma unroll
        for (int e2 = 0; e2 < 4; ++e2) {
            __half ha = __float2half_rn(hn[e2 * 2]);
            __half hb = __float2half_rn(hn[e2 * 2 + 1]);
            ph[e2] = (uint32_t)__half_as_ushort(ha) | ((uint32_t)__half_as_ushort(hb) << 16);
        }
        *(uint4*)(&g_h[wr][off]) = make_uint4(ph[0], ph[1], ph[2], ph[3]);
    }
}

// ---------------- decoder projection ----------------
__global__ __launch_bounds__(256)
void proj_kernel(int hbuf,
                 const float* __restrict__ W_out,
                 const float* __restrict__ b_out,
                 float* __restrict__ outp)
{
    int lane = threadIdx.x & 31;
    int w = threadIdx.x >> 5;
    int d = blockIdx.x * 8 + w;
    int r0 = blockIdx.y * 8;
    const __half* hp = g_h[hbuf];
    int k0 = lane * 32;

    float wv[32];
    {
        const float4* wp = (const float4*)(W_out + (size_t)d * CH + k0);
#pragma unroll
        for (int q = 0; q < 8; ++q) {
            float4 f = wp[q];
            wv[q * 4 + 0] = f.x; wv[q * 4 + 1] = f.y; wv[q * 4 + 2] = f.z; wv[q * 4 + 3] = f.w;
        }
    }
    float acc[8];
#pragma unroll
    for (int r = 0; r < 8; ++r) {
        const uint4* hq = (const uint4*)(hp + (size_t)(r0 + r) * CH + k0);
        float s = 0.0f;
#pragma unroll
        for (int q = 0; q < 4; ++q) {
            uint4 hv = hq[q];
            const __half2* h2 = (const __half2*)&hv;
#pragma unroll
            for (int e = 0; e < 4; ++e) {
                float2 a = __half22float2(h2[e]);
                int kk = q * 8 + e * 2;
                s += a.x * wv[kk] + a.y * wv[kk + 1];
            }
        }
        acc[r] = s;
    }
#pragma unroll
    for (int r = 0; r < 8; ++r) {
#pragma unroll
        for (int off = 16; off > 0; off >>= 1)
            acc[r] += __shfl_xor_sync(0xFFFFFFFFu, acc[r], off);
    }
    if (lane == 0) {
        float bo = b_out[d];
#pragma unroll
        for (int r = 0; r < 8; ++r) {
            float y = acc[r] + bo;
            int row = r0 + r;
            outp[(size_t)row * CML * CD + d] = y;
            g_xd[(size_t)row * XSTR + d] = __float2half_rn(y);
        }
    }
}

extern "C" void kernel_launch(void* const* d_in, const int* in_sizes, int n_in,
                              void* d_out, int out_size)
{
    (void)in_sizes; (void)n_in; (void)out_size;
    const float* src   = (const float*)d_in[0];
    const float* W_ih  = (const float*)d_in[1];
    const float* W_hh  = (const float*)d_in[2];
    const float* b_ih  = (const float*)d_in[3];
    const float* b_hh  = (const float*)d_in[4];
    const float* W_out = (const float*)d_in[5];
    const float* b_out = (const float*)d_in[6];
    float* out = (float*)d_out;

    static int once = 0;
    if (!once) {
        cudaFuncSetAttribute(lstm_step, cudaFuncAttributeMaxDynamicSharedMemorySize, SMEM_STEP);
        once = 1;
    }

    init_kernel<<<(CB * CH + 255) / 256, 256>>>(b_ih, b_hh);
    {
        size_t tot = (size_t)CS * CB * XSTR;
        src_split_kernel<<<(unsigned)((tot + 255) / 256), 256>>>(src);
    }
    {
        int tot = NT * 4 * NCH * 4 * 128;
        prep_w_kernel<<<(tot + 255) / 256, 256>>>(W_ih, W_hh);
    }

    dim3 sgrid(NT, CB / MT);   // 32 x 8 = 256 CTAs
    dim3 pgrid(27, CB / 8);    // 27 x 64

    int p = 0;
    for (int t = 0; t < CS; ++t) {
        lstm_step<<<sgrid, 256, SMEM_STEP>>>(0, t, p, p ^ 1);
        p ^= 1;
    }
    for (int s = 0; s < CML; ++s) {
        if (s == 0) lstm_step<<<sgrid, 256, SMEM_STEP>>>(0, CS - 1, p, p ^ 1);
        else        lstm_step<<<sgrid, 256, SMEM_STEP>>>(1, 0, p, p ^ 1);
        proj_kernel<<<pgrid, 256>>>(p ^ 1, W_out, b_out, out + (size_t)s * CD);
        p ^= 1;
    }
}